// round 9
// baseline (speedup 1.0000x reference)
#include <cuda_runtime.h>
#include <cuda_fp16.h>
#include <cstdint>

#define N_Q   50000
#define M_S   50000
#define KNNB  32
#define KPN   15
#define CIN   64
#define COUT  128
#define KDIM  (KPN * CIN)      // 960
#define KP_EXT_INV (1.0f / 1.2f)
#define BM    128
#define NBLK  391              // ceil(50000/128)

// Scratch (zero-initialized device globals)
__device__ __align__(16) __half g_sf16[(size_t)M_S * CIN];      // fp16 features
__device__ __align__(16) __half g_wtT16[(size_t)COUT * KDIM];   // W^T [n][k]
__device__ float g_rs[M_S];                                     // row sums

// ---------------------------------------------------------------------------
// k0: blocks 0..3124: s_feats rowsum + fp16 convert (float4, 2 rows/warp)
//     blocks 3125..3139: W[960,128] -> W^T[128,960] fp16 via smem transpose
// ---------------------------------------------------------------------------
__global__ __launch_bounds__(256) void k0_prep(
    const float* __restrict__ sf, const float* __restrict__ W)
{
    int b = blockIdx.x;
    if (b < 3125) {
        int wid = threadIdx.x >> 5, lane = threadIdx.x & 31;
        int half_w = lane >> 4;             // 0/1 -> row select
        int l16 = lane & 15;
        int row = b * 16 + wid * 2 + half_w;
        float4 v = *(const float4*)&sf[(size_t)row * CIN + l16 * 4];
        __half2 h0 = __floats2half2_rn(v.x, v.y);
        __half2 h1 = __floats2half2_rn(v.z, v.w);
        *reinterpret_cast<uint2*>(&g_sf16[(size_t)row * CIN + l16 * 4]) =
            make_uint2(*(unsigned*)&h0, *(unsigned*)&h1);
        float s = (v.x + v.y) + (v.z + v.w);
        #pragma unroll
        for (int off = 8; off; off >>= 1)
            s += __shfl_xor_sync(0xffffffffu, s, off);
        if (l16 == 0) g_rs[row] = s;
    } else {
        __shared__ __half tr[128][72];
        int tid = threadIdx.x;
        int k0w = (b - 3125) * 64;
        #pragma unroll
        for (int i = 0; i < 8; i++) {
            int lin = tid + i * 256;            // 0..2047
            int r  = lin >> 5;                  // k-local 0..63
            int c4 = (lin & 31) * 4;            // n
            float4 v = *(const float4*)&W[(size_t)(k0w + r) * COUT + c4];
            tr[c4 + 0][r] = __float2half_rn(v.x);
            tr[c4 + 1][r] = __float2half_rn(v.y);
            tr[c4 + 2][r] = __float2half_rn(v.z);
            tr[c4 + 3][r] = __float2half_rn(v.w);
        }
        __syncthreads();
        int n = tid >> 1, part = (tid & 1) * 32;
        const uint4* src = reinterpret_cast<const uint4*>(&tr[n][part]);
        uint4* dst = reinterpret_cast<uint4*>(&g_wtT16[(size_t)n * KDIM + k0w + part]);
        #pragma unroll
        for (int j = 0; j < 4; j++) dst[j] = src[j];
    }
}

// ---------------------------------------------------------------------------
// fused: per 128-query tile — gather+aggregate kf_e into smem (double buf),
// HMMA against W_e, accumulate 15 chunks, scaled epilogue. 256 thr, 8 warps.
// ---------------------------------------------------------------------------
// smem layout (from 1024-aligned base):
#define SM_KF    0            // 2 x 128 x 128 B          (32768)
#define SM_WB    32768        // 128 x 128 B              (16384)
#define SM_RX    49152        // 128*32 f32               (16384)
#define SM_RY    65536
#define SM_RZ    81920
#define SM_ID    98304        // 128*32 u16               (8192)
#define SM_INV   106496       // 128 f32                  (512)
#define SM_KP    107008       // 45 f32                   (192)
#define SM_TOT   (107200 + 1024)

extern __shared__ __align__(16) unsigned char fz_dsm[];

__device__ __forceinline__ void cpa16s(unsigned dst, const __half* src)
{
    asm volatile("cp.async.cg.shared.global [%0], [%1], 16;\n" :: "r"(dst), "l"(src));
}

__global__ __launch_bounds__(256, 2) void k_fused(
    const float* __restrict__ q_pts, const float* __restrict__ s_pts,
    const int* __restrict__ nidx, const float* __restrict__ kpts,
    float* __restrict__ out)
{
    const int tid  = threadIdx.x;
    const int wid  = tid >> 5;
    const int lane = tid & 31;
    const int m0   = blockIdx.x * BM;

    unsigned raw  = (unsigned)__cvta_generic_to_shared(fz_dsm);
    unsigned base = (raw + 1023u) & ~1023u;
    unsigned char* sm = fz_dsm + (base - raw);

    float* relx = (float*)(sm + SM_RX);
    float* rely = (float*)(sm + SM_RY);
    float* relz = (float*)(sm + SM_RZ);
    unsigned short* ids = (unsigned short*)(sm + SM_ID);
    float* inv_s = (float*)(sm + SM_INV);
    float* kp_s  = (float*)(sm + SM_KP);
    const unsigned kf_u = base + SM_KF;
    const unsigned wb_u = base + SM_WB;

    if (tid < KPN * 3) kp_s[tid] = kpts[tid];

    // ---- setup: rel positions, ids, validity for 16 queries per warp ----
    #pragma unroll 1
    for (int i = 0; i < 16; i++) {
        int qq  = wid * 16 + i;
        int qid = m0 + qq;
        int qg  = qid < N_Q ? qid : N_Q - 1;
        int id  = nidx[qg * KNNB + lane];
        bool valid = id < M_S;
        int idc = valid ? id : 0;
        float px = valid ? s_pts[idc * 3 + 0] : 1e6f;
        float py = valid ? s_pts[idc * 3 + 1] : 1e6f;
        float pz = valid ? s_pts[idc * 3 + 2] : 1e6f;
        float qx = __ldg(&q_pts[qg * 3 + 0]);
        float qy = __ldg(&q_pts[qg * 3 + 1]);
        float qz = __ldg(&q_pts[qg * 3 + 2]);
        relx[qq * KNNB + lane] = px - qx;
        rely[qq * KNNB + lane] = py - qy;
        relz[qq * KNNB + lane] = pz - qz;
        ids[qq * KNNB + lane]  = (unsigned short)idc;
        bool flag = valid && (g_rs[idc] > 0.0f);
        unsigned bal = __ballot_sync(0xffffffffu, flag);
        if (lane == 0) {
            int c2 = __popc(bal);
            inv_s[qq] = 1.0f / (float)(c2 > 0 ? c2 : 1);
        }
        // mark invalid (shadow) so h<=0: overwrite rel with huge
        if (!valid) {
            relx[qq * KNNB + lane] = 1e6f;
            rely[qq * KNNB + lane] = 1e6f;
            relz[qq * KNNB + lane] = 1e6f;
        }
    }
    __syncthreads();

    const __half2* fb2 = reinterpret_cast<const __half2*>(g_sf16) + lane;

    // ---- aggregation lambda: kf_e for this block into buffer buf ----
    auto aggregate = [&](int e, int buf) {
        float kx = kp_s[e * 3 + 0];
        float ky = kp_s[e * 3 + 1];
        float kz = kp_s[e * 3 + 2];
        unsigned kfb = kf_u + buf * (BM * 128);
        #pragma unroll 1
        for (int i = 0; i < 16; i++) {
            int qq = wid * 16 + i;
            float dx = relx[qq * KNNB + lane] - kx;
            float dy = rely[qq * KNNB + lane] - ky;
            float dz = relz[qq * KNNB + lane] - kz;
            float d2 = fmaf(dx, dx, fmaf(dy, dy, fmaf(dz, dz, 1e-8f)));
            float h  = 1.0f - sqrtf(d2) * KP_EXT_INV;
            unsigned m = __ballot_sync(0xffffffffu, h > 0.0f);
            int idv = ids[qq * KNNB + lane];
            unsigned long long acc = 0ull;
            while (m) {
                int nb = __ffs(m) - 1;      // warp-uniform
                m &= m - 1;
                float hh = __shfl_sync(0xffffffffu, h, nb);
                int   ii = __shfl_sync(0xffffffffu, idv, nb);
                float2 f = __half22float2(fb2[ii * (CIN / 2)]);
                unsigned long long hv, f2;
                asm("mov.b64 %0, {%1, %1};" : "=l"(hv) : "f"(hh));
                asm("mov.b64 %0, {%1, %2};" : "=l"(f2) : "f"(f.x), "f"(f.y));
                asm("fma.rn.f32x2 %0, %1, %2, %0;" : "+l"(acc) : "l"(f2), "l"(hv));
            }
            float lo, hi;
            asm("mov.b64 {%0, %1}, %2;" : "=f"(lo), "=f"(hi) : "l"(acc));
            __half2 hv2 = __floats2half2_rn(lo, hi);
            unsigned addr = kfb + qq * 128 +
                            (((lane >> 2) ^ (qq & 7)) << 4) + (lane & 3) * 4;
            asm volatile("st.shared.b32 [%0], %1;"
                         :: "r"(addr), "r"(*(unsigned*)&hv2));
        }
    };

    // ---- W_e loader: 128 rows x 128 B into wbuf (swizzled) ----
    auto loadW = [&](int e) {
        const __half* B = g_wtT16 + e * (CIN);
        #pragma unroll
        for (int it = 0; it < 4; it++) {
            int lin = tid + it * 256;            // 0..1023
            int row = lin >> 3, gr = lin & 7;
            int gsw = gr ^ (row & 7);
            cpa16s(wb_u + row * 128 + gsw * 16,
                   B + (size_t)row * KDIM + gr * 8);
        }
        asm volatile("cp.async.commit_group;");
    };

    // accumulators
    const int g = lane >> 2;
    const int t = lane & 3;
    const int warp_m = wid & 1;
    const int warp_n = wid >> 1;

    float c[4][4][4];
    #pragma unroll
    for (int mt = 0; mt < 4; mt++)
        #pragma unroll
        for (int nt = 0; nt < 4; nt++)
            #pragma unroll
            for (int r = 0; r < 4; r++) c[mt][nt][r] = 0.0f;

    // prologue
    loadW(0);
    aggregate(0, 0);
    asm volatile("cp.async.wait_group 0;");
    __syncthreads();

    for (int e = 0; e < KPN; e++) {
        unsigned as = kf_u + (e & 1) * (BM * 128);
        unsigned bs = wb_u;

        #pragma unroll
        for (int kq = 0; kq < 4; kq++) {
            unsigned a_[4][4], b_[4][2];
            #pragma unroll
            for (int mt = 0; mt < 4; mt++) {
                int row = warp_m * 64 + mt * 16 + (lane & 15);
                int gr  = kq * 2 + (lane >> 4);
                unsigned addr = as + (row * 8 + (gr ^ (row & 7))) * 16;
                asm volatile(
                    "ldmatrix.sync.aligned.m8n8.x4.shared.b16 {%0,%1,%2,%3}, [%4];"
                    : "=r"(a_[mt][0]), "=r"(a_[mt][1]),
                      "=r"(a_[mt][2]), "=r"(a_[mt][3]) : "r"(addr));
            }
            #pragma unroll
            for (int cb = 0; cb < 2; cb++) {
                int which  = lane >> 3;
                int nt_loc = cb * 2 + (which >> 1);
                int kh     = which & 1;
                int row = warp_n * 32 + nt_loc * 8 + (lane & 7);
                int gr  = kq * 2 + kh;
                unsigned addr = bs + (row * 8 + (gr ^ (row & 7))) * 16;
                asm volatile(
                    "ldmatrix.sync.aligned.m8n8.x4.shared.b16 {%0,%1,%2,%3}, [%4];"
                    : "=r"(b_[cb * 2][0]),     "=r"(b_[cb * 2][1]),
                      "=r"(b_[cb * 2 + 1][0]), "=r"(b_[cb * 2 + 1][1]) : "r"(addr));
            }
            #pragma unroll
            for (int mt = 0; mt < 4; mt++)
                #pragma unroll
                for (int nt = 0; nt < 4; nt++)
                    asm volatile(
                        "mma.sync.aligned.m16n8k16.row.col.f32.f16.f16.f32 "
                        "{%0,%1,%2,%3}, {%4,%5,%6,%7}, {%8,%9}, {%0,%1,%2,%3};"
                        : "+f"(c[mt][nt][0]), "+f"(c[mt][nt][1]),
                          "+f"(c[mt][nt][2]), "+f"(c[mt][nt][3])
                        : "r"(a_[mt][0]), "r"(a_[mt][1]),
                          "r"(a_[mt][2]), "r"(a_[mt][3]),
                          "r"(b_[nt][0]), "r"(b_[nt][1]));
        }

        __syncthreads();          // all warps done reading kf[e&1] + wbuf
        if (e + 1 < KPN) {
            loadW(e + 1);
            aggregate(e + 1, (e + 1) & 1);
            asm volatile("cp.async.wait_group 0;");
        }
        __syncthreads();
    }

    // ---- epilogue ----
    #pragma unroll
    for (int mt = 0; mt < 4; mt++) {
        int rl0 = warp_m * 64 + mt * 16 + g;
        int rl1 = rl0 + 8;
        int r0 = m0 + rl0, r1 = m0 + rl1;
        float inv0 = inv_s[rl0];
        float inv1 = inv_s[rl1];
        #pragma unroll
        for (int nt = 0; nt < 4; nt++) {
            int col = warp_n * 32 + nt * 8 + t * 2;
            if (r0 < N_Q)
                *(float2*)&out[(size_t)r0 * COUT + col] =
                    make_float2(c[mt][nt][0] * inv0, c[mt][nt][1] * inv0);
            if (r1 < N_Q)
                *(float2*)&out[(size_t)r1 * COUT + col] =
                    make_float2(c[mt][nt][2] * inv1, c[mt][nt][3] * inv1);
        }
    }
}

// ---------------------------------------------------------------------------
extern "C" void kernel_launch(void* const* d_in, const int* in_sizes, int n_in,
                              void* d_out, int out_size)
{
    const float* q_pts   = (const float*)d_in[0];
    const float* s_pts   = (const float*)d_in[1];
    const float* s_feats = (const float*)d_in[2];
    const int*   nidx    = (const int*)  d_in[3];
    const float* W       = (const float*)d_in[4];
    const float* kpts    = (const float*)d_in[5];
    float* out = (float*)d_out;

    cudaFuncSetAttribute(k_fused,
        cudaFuncAttributeMaxDynamicSharedMemorySize, SM_TOT);

    k0_prep<<<3140, 256>>>(s_feats, W);
    k_fused<<<NBLK, 256, SM_TOT>>>(q_pts, s_pts, nidx, kpts, out);
}

// round 10
// speedup vs baseline: 1.0289x; 1.0289x over previous
#include <cuda_runtime.h>
#include <cuda_fp16.h>
#include <cstdint>

#define N_Q   50000
#define M_S   50000
#define KNNB  32
#define KPN   15
#define CIN   64
#define COUT  128
#define KDIM  (KPN * CIN)      // 960
#define KP_EXT_INV (1.0f / 1.2f)
#define BM    128
#define NBLK  391              // ceil(50000/128)
#define PSLOT 80               // pair slots per query (mean 28, ~10 sigma)

// Scratch (zero-initialized device globals)
__device__ __align__(16) __half g_sf16[(size_t)M_S * CIN];      // fp16 features
__device__ __align__(16) __half g_wtT16[(size_t)COUT * KDIM];   // W^T [n][k]
__device__ float g_rs[M_S];                                     // row sums

// ---------------------------------------------------------------------------
// k0: blocks 0..3124: s_feats rowsum + fp16 convert (float4, 2 rows/warp)
//     blocks 3125..3139: W[960,128] -> W^T[128,960] fp16 via smem transpose
// ---------------------------------------------------------------------------
__global__ __launch_bounds__(256) void k0_prep(
    const float* __restrict__ sf, const float* __restrict__ W)
{
    int b = blockIdx.x;
    if (b < 3125) {
        int wid = threadIdx.x >> 5, lane = threadIdx.x & 31;
        int half_w = lane >> 4;
        int l16 = lane & 15;
        int row = b * 16 + wid * 2 + half_w;
        float4 v = *(const float4*)&sf[(size_t)row * CIN + l16 * 4];
        __half2 h0 = __floats2half2_rn(v.x, v.y);
        __half2 h1 = __floats2half2_rn(v.z, v.w);
        *reinterpret_cast<uint2*>(&g_sf16[(size_t)row * CIN + l16 * 4]) =
            make_uint2(*(unsigned*)&h0, *(unsigned*)&h1);
        float s = (v.x + v.y) + (v.z + v.w);
        #pragma unroll
        for (int off = 8; off; off >>= 1)
            s += __shfl_xor_sync(0xffffffffu, s, off);
        if (l16 == 0) g_rs[row] = s;
    } else {
        __shared__ __half tr[128][72];
        int tid = threadIdx.x;
        int k0w = (b - 3125) * 64;
        #pragma unroll
        for (int i = 0; i < 8; i++) {
            int lin = tid + i * 256;
            int r  = lin >> 5;
            int c4 = (lin & 31) * 4;
            float4 v = *(const float4*)&W[(size_t)(k0w + r) * COUT + c4];
            tr[c4 + 0][r] = __float2half_rn(v.x);
            tr[c4 + 1][r] = __float2half_rn(v.y);
            tr[c4 + 2][r] = __float2half_rn(v.z);
            tr[c4 + 3][r] = __float2half_rn(v.w);
        }
        __syncthreads();
        int n = tid >> 1, part = (tid & 1) * 32;
        const uint4* src = reinterpret_cast<const uint4*>(&tr[n][part]);
        uint4* dst = reinterpret_cast<uint4*>(&g_wtT16[(size_t)n * KDIM + k0w + part]);
        #pragma unroll
        for (int j = 0; j < 4; j++) dst[j] = src[j];
    }
}

// ---------------------------------------------------------------------------
// fused v2: setup builds e-grouped pair lists once; per-e loop overlaps
// W cp.async + MMA(e) + aggregate(e+1) with double-buffered kf and W.
// ---------------------------------------------------------------------------
// smem layout from 1024-aligned base:
#define SM_KF   0              // 2 x 16384
#define SM_WB   32768          // 2 x 16384
#define SM_PR   65536          // 128 q x 80 slots x 4 B = 40960
#define SM_OFF  106496         // 128 x 16 u8 = 2048
#define SM_INV  108544         // 128 f32 = 512
#define SM_KP   109056         // 45 f32
#define SM_TOT  (109248 + 1024)

extern __shared__ __align__(16) unsigned char fz_dsm[];

__device__ __forceinline__ void cpa16s(unsigned dst, const __half* src)
{
    asm volatile("cp.async.cg.shared.global [%0], [%1], 16;\n" :: "r"(dst), "l"(src));
}

__global__ __launch_bounds__(256, 2) void k_fused(
    const float* __restrict__ q_pts, const float* __restrict__ s_pts,
    const int* __restrict__ nidx, const float* __restrict__ kpts,
    float* __restrict__ out)
{
    const int tid  = threadIdx.x;
    const int wid  = tid >> 5;
    const int lane = tid & 31;
    const int m0   = blockIdx.x * BM;

    unsigned raw  = (unsigned)__cvta_generic_to_shared(fz_dsm);
    unsigned base = (raw + 1023u) & ~1023u;
    unsigned char* sm = fz_dsm + (base - raw);

    const unsigned kf_u = base + SM_KF;
    const unsigned wb_u = base + SM_WB;
    unsigned*       pairs = (unsigned*)(sm + SM_PR);
    unsigned char*  offs  = (unsigned char*)(sm + SM_OFF);
    float*          inv_s = (float*)(sm + SM_INV);
    float*          kp_s  = (float*)(sm + SM_KP);

    if (tid < KPN * 3) kp_s[tid] = kpts[tid];
    __syncthreads();

    // ---- setup: per warp 16 queries; lane = neighbor; build pair lists ----
    const unsigned below = (1u << lane) - 1u;
    #pragma unroll 1
    for (int i = 0; i < 16; i++) {
        int qq  = wid * 16 + i;
        int qid = m0 + qq;
        int qg  = qid < N_Q ? qid : N_Q - 1;
        int id  = nidx[qg * KNNB + lane];
        bool valid = id < M_S;
        int idc = valid ? id : 0;
        float px = s_pts[idc * 3 + 0];
        float py = s_pts[idc * 3 + 1];
        float pz = s_pts[idc * 3 + 2];
        float qx = __ldg(&q_pts[qg * 3 + 0]);
        float qy = __ldg(&q_pts[qg * 3 + 1]);
        float qz = __ldg(&q_pts[qg * 3 + 2]);
        float rx = valid ? px - qx : 1e6f;
        float ry = valid ? py - qy : 1e6f;
        float rz = valid ? pz - qz : 1e6f;

        bool flag = valid && (g_rs[idc] > 0.0f);
        unsigned bal = __ballot_sync(0xffffffffu, flag);
        if (lane == 0) {
            int c2 = __popc(bal);
            inv_s[qq] = 1.0f / (float)(c2 > 0 ? c2 : 1);
        }

        unsigned* pq = pairs + qq * PSLOT;
        int bcnt = 0;
        #pragma unroll
        for (int e = 0; e < KPN; e++) {
            float dx = rx - kp_s[e * 3 + 0];
            float dy = ry - kp_s[e * 3 + 1];
            float dz = rz - kp_s[e * 3 + 2];
            float d2 = fmaf(dx, dx, fmaf(dy, dy, fmaf(dz, dz, 1e-8f)));
            float h  = 1.0f - sqrtf(d2) * KP_EXT_INV;
            unsigned m = __ballot_sync(0xffffffffu, h > 0.0f);
            offs[qq * 16 + e] = (unsigned char)bcnt;
            if (m & (1u << lane)) {
                int pos = bcnt + __popc(m & below);
                if (pos < PSLOT) {
                    unsigned pv =
                        ((unsigned)__half_as_ushort(__float2half_rn(h)) << 16) |
                        (unsigned)idc;
                    pq[pos] = pv;
                }
            }
            bcnt += __popc(m);
            if (bcnt > PSLOT) bcnt = PSLOT;
        }
        offs[qq * 16 + 15] = (unsigned char)bcnt;
    }
    __syncthreads();

    // ---- aggregation: lane = channel-pair; flat counted loops, MLP LDGs ----
    auto aggregate = [&](int e, int buf) {
        unsigned kfb = kf_u + buf * (BM * 128);
        #pragma unroll 2
        for (int i = 0; i < 16; i++) {
            int qq = wid * 16 + i;
            int s0 = offs[qq * 16 + e];
            int s1 = offs[qq * 16 + e + 1];
            const unsigned* pq = pairs + qq * PSLOT;
            unsigned long long acc = 0ull;
            #pragma unroll 2
            for (int j = s0; j < s1; j++) {
                unsigned pv = pq[j];                 // LDS.32 broadcast
                float hf = __half2float(__ushort_as_half((unsigned short)(pv >> 16)));
                int id = pv & 0xFFFFu;
                __half2 fh = *(reinterpret_cast<const __half2*>(
                                   g_sf16 + (size_t)id * CIN) + lane);
                float2 f = __half22float2(fh);
                unsigned long long hv, f2;
                asm("mov.b64 %0, {%1, %1};" : "=l"(hv) : "f"(hf));
                asm("mov.b64 %0, {%1, %2};" : "=l"(f2) : "f"(f.x), "f"(f.y));
                asm("fma.rn.f32x2 %0, %1, %2, %0;" : "+l"(acc) : "l"(f2), "l"(hv));
            }
            float lo, hi;
            asm("mov.b64 {%0, %1}, %2;" : "=f"(lo), "=f"(hi) : "l"(acc));
            __half2 hv2 = __floats2half2_rn(lo, hi);
            unsigned addr = kfb + qq * 128 +
                            (((lane >> 2) ^ (qq & 7)) << 4) + (lane & 3) * 4;
            asm volatile("st.shared.b32 [%0], %1;"
                         :: "r"(addr), "r"(*(unsigned*)&hv2));
        }
    };

    // ---- W_e loader into double buffer ----
    auto loadW = [&](int e) {
        const __half* B = g_wtT16 + e * CIN;
        unsigned wb = wb_u + (e & 1) * (BM * 128);
        #pragma unroll
        for (int it = 0; it < 4; it++) {
            int lin = tid + it * 256;
            int row = lin >> 3, gr = lin & 7;
            int gsw = gr ^ (row & 7);
            cpa16s(wb + row * 128 + gsw * 16, B + (size_t)row * KDIM + gr * 8);
        }
        asm volatile("cp.async.commit_group;");
    };

    const int g = lane >> 2;
    const int t = lane & 3;
    const int warp_m = wid & 1;
    const int warp_n = wid >> 1;

    float c[4][4][4];
    #pragma unroll
    for (int mt = 0; mt < 4; mt++)
        #pragma unroll
        for (int nt = 0; nt < 4; nt++)
            #pragma unroll
            for (int r = 0; r < 4; r++) c[mt][nt][r] = 0.0f;

    // prologue
    loadW(0);
    aggregate(0, 0);
    asm volatile("cp.async.wait_group 0;");
    __syncthreads();

    for (int e = 0; e < KPN; e++) {
        if (e + 1 < KPN) loadW(e + 1);        // async, other W buffer

        unsigned as = kf_u + (e & 1) * (BM * 128);
        unsigned bs = wb_u + (e & 1) * (BM * 128);

        #pragma unroll
        for (int kq = 0; kq < 4; kq++) {
            unsigned a_[4][4], b_[4][2];
            #pragma unroll
            for (int mt = 0; mt < 4; mt++) {
                int row = warp_m * 64 + mt * 16 + (lane & 15);
                int gr  = kq * 2 + (lane >> 4);
                unsigned addr = as + (row * 8 + (gr ^ (row & 7))) * 16;
                asm volatile(
                    "ldmatrix.sync.aligned.m8n8.x4.shared.b16 {%0,%1,%2,%3}, [%4];"
                    : "=r"(a_[mt][0]), "=r"(a_[mt][1]),
                      "=r"(a_[mt][2]), "=r"(a_[mt][3]) : "r"(addr));
            }
            #pragma unroll
            for (int cb = 0; cb < 2; cb++) {
                int which  = lane >> 3;
                int nt_loc = cb * 2 + (which >> 1);
                int kh     = which & 1;
                int row = warp_n * 32 + nt_loc * 8 + (lane & 7);
                int gr  = kq * 2 + kh;
                unsigned addr = bs + (row * 8 + (gr ^ (row & 7))) * 16;
                asm volatile(
                    "ldmatrix.sync.aligned.m8n8.x4.shared.b16 {%0,%1,%2,%3}, [%4];"
                    : "=r"(b_[cb * 2][0]),     "=r"(b_[cb * 2][1]),
                      "=r"(b_[cb * 2 + 1][0]), "=r"(b_[cb * 2 + 1][1]) : "r"(addr));
            }
            #pragma unroll
            for (int mt = 0; mt < 4; mt++)
                #pragma unroll
                for (int nt = 0; nt < 4; nt++)
                    asm volatile(
                        "mma.sync.aligned.m16n8k16.row.col.f32.f16.f16.f32 "
                        "{%0,%1,%2,%3}, {%4,%5,%6,%7}, {%8,%9}, {%0,%1,%2,%3};"
                        : "+f"(c[mt][nt][0]), "+f"(c[mt][nt][1]),
                          "+f"(c[mt][nt][2]), "+f"(c[mt][nt][3])
                        : "r"(a_[mt][0]), "r"(a_[mt][1]),
                          "r"(a_[mt][2]), "r"(a_[mt][3]),
                          "r"(b_[nt][0]), "r"(b_[nt][1]));
        }

        if (e + 1 < KPN) aggregate(e + 1, (e + 1) & 1);   // other kf buffer
        asm volatile("cp.async.wait_group 0;");
        __syncthreads();
    }

    // ---- epilogue ----
    #pragma unroll
    for (int mt = 0; mt < 4; mt++) {
        int rl0 = warp_m * 64 + mt * 16 + g;
        int rl1 = rl0 + 8;
        int r0 = m0 + rl0, r1 = m0 + rl1;
        float inv0 = inv_s[rl0];
        float inv1 = inv_s[rl1];
        #pragma unroll
        for (int nt = 0; nt < 4; nt++) {
            int col = warp_n * 32 + nt * 8 + t * 2;
            if (r0 < N_Q)
                *(float2*)&out[(size_t)r0 * COUT + col] =
                    make_float2(c[mt][nt][0] * inv0, c[mt][nt][1] * inv0);
            if (r1 < N_Q)
                *(float2*)&out[(size_t)r1 * COUT + col] =
                    make_float2(c[mt][nt][2] * inv1, c[mt][nt][3] * inv1);
        }
    }
}

// ---------------------------------------------------------------------------
extern "C" void kernel_launch(void* const* d_in, const int* in_sizes, int n_in,
                              void* d_out, int out_size)
{
    const float* q_pts   = (const float*)d_in[0];
    const float* s_pts   = (const float*)d_in[1];
    const float* s_feats = (const float*)d_in[2];
    const int*   nidx    = (const int*)  d_in[3];
    const float* W       = (const float*)d_in[4];
    const float* kpts    = (const float*)d_in[5];
    float* out = (float*)d_out;

    cudaFuncSetAttribute(k_fused,
        cudaFuncAttributeMaxDynamicSharedMemorySize, SM_TOT);

    k0_prep<<<3140, 256>>>(s_feats, W);
    k_fused<<<NBLK, 256, SM_TOT>>>(q_pts, s_pts, nidx, kpts, out);
}

// round 11
// speedup vs baseline: 1.4349x; 1.3946x over previous
#include <cuda_runtime.h>
#include <cuda_fp16.h>
#include <cstdint>

#define N_Q   50000
#define M_S   50000
#define KNNB  32
#define KPN   15
#define CIN   64
#define COUT  128
#define KDIM  (KPN * CIN)      // 960
#define KP_EXT_INV (1.0f / 1.2f)
#define M_PAD 50048

// Scratch (zero-initialized device globals; padding rows never written)
__device__ __align__(1024) __half g_kf16[(size_t)M_PAD * KDIM];  // A [m][k]
__device__ __align__(1024) __half g_wtT16[(size_t)COUT * KDIM];  // W^T [n][k]
__device__ float g_inv[M_PAD];
__device__ float g_rs[M_S];

// ---------------------------------------------------------------------------
// k0: blocks 0..390: rowsum of s_feats (2 threads/row, float4 MLP=8)
//     blocks 391..405: W[960,128] -> W^T[128,960] fp16 via smem transpose
// ---------------------------------------------------------------------------
__global__ __launch_bounds__(256) void k0_prep(
    const float* __restrict__ sf, const float* __restrict__ W)
{
    int b = blockIdx.x;
    if (b < 391) {
        int tid = threadIdx.x;
        int row = b * 128 + (tid >> 1);
        int part = tid & 1;
        if (row < M_S) {
            const float4* p = (const float4*)&sf[(size_t)row * CIN + part * 32];
            float s = 0.0f;
            #pragma unroll
            for (int i = 0; i < 8; i++) {
                float4 v = p[i];
                s += (v.x + v.y) + (v.z + v.w);
            }
            s += __shfl_xor_sync(0xffffffffu, s, 1);
            if (part == 0) g_rs[row] = s;
        }
    } else {
        __shared__ __half tr[128][72];
        int tid = threadIdx.x;
        int k0w = (b - 391) * 64;
        #pragma unroll
        for (int i = 0; i < 8; i++) {
            int lin = tid + i * 256;            // 0..2047
            int r  = lin >> 5;                  // k-local 0..63
            int c4 = (lin & 31) * 4;            // n
            float4 v = *(const float4*)&W[(size_t)(k0w + r) * COUT + c4];
            tr[c4 + 0][r] = __float2half_rn(v.x);
            tr[c4 + 1][r] = __float2half_rn(v.y);
            tr[c4 + 2][r] = __float2half_rn(v.z);
            tr[c4 + 3][r] = __float2half_rn(v.w);
        }
        __syncthreads();
        int n = tid >> 1, part = (tid & 1) * 32;
        const uint4* src = reinterpret_cast<const uint4*>(&tr[n][part]);
        uint4* dst = reinterpret_cast<uint4*>(&g_wtT16[(size_t)n * KDIM + k0w + part]);
        #pragma unroll
        for (int j = 0; j < 4; j++) dst[j] = src[j];
    }
}

// ---------------------------------------------------------------------------
// k1: gather + sparse kernel-point aggregation (round-5, proven 41us).
// Warp per query; (h,id) pair list grouped by kernel point; f32 LDG gather.
// ---------------------------------------------------------------------------
#define NW1 8
#define PLSZ (KNNB * KPN + 32)
__global__ __launch_bounds__(NW1 * 32) void k1_gather(
    const float* __restrict__ q_pts, const float* __restrict__ s_pts,
    const float* __restrict__ s_feats, const int* __restrict__ nidx,
    const float* __restrict__ kpts)
{
    __shared__ float  kp_s[KPN * 3];
    __shared__ float2 pair_s[NW1][PLSZ];

    const int tid  = threadIdx.x;
    const int wid  = tid >> 5;
    const int lane = tid & 31;
    const int qid  = blockIdx.x * NW1 + wid;        // grid = 6250 exact

    if (tid < KPN * 3) kp_s[tid] = kpts[tid];
    __syncthreads();

    const int my_id = nidx[qid * KNNB + lane];

    const float qx = q_pts[qid * 3 + 0];
    const float qy = q_pts[qid * 3 + 1];
    const float qz = q_pts[qid * 3 + 2];
    float px, py, pz;
    if (my_id < M_S) {
        px = s_pts[my_id * 3 + 0];
        py = s_pts[my_id * 3 + 1];
        pz = s_pts[my_id * 3 + 2];
    } else { px = py = pz = 1e6f; }
    const float rx = px - qx, ry = py - qy, rz = pz - qz;

    float2* plist = pair_s[wid];
    const unsigned below = (1u << lane) - 1u;
    const float idf = __int_as_float(my_id);
    int cnt[KPN];
    int base = 0;
    #pragma unroll
    for (int e = 0; e < KPN; e++) {
        float dx = rx - kp_s[e * 3 + 0];
        float dy = ry - kp_s[e * 3 + 1];
        float dz = rz - kp_s[e * 3 + 2];
        float d2 = fmaf(dx, dx, fmaf(dy, dy, fmaf(dz, dz, 1e-8f)));
        float h  = 1.0f - sqrtf(d2) * KP_EXT_INV;
        unsigned m = __ballot_sync(0xffffffffu, h > 0.0f);
        int pos = (m & (1u << lane)) ? base + __popc(m & below)
                                     : KNNB * KPN + lane;
        plist[pos] = make_float2(h, idf);
        cnt[e] = __popc(m);
        base += cnt[e];
    }

    int idc = my_id < M_S ? my_id : 0;
    bool flag = (my_id < M_S) && (g_rs[idc] > 0.0f);
    unsigned bal = __ballot_sync(0xffffffffu, flag);
    if (lane == 0) {
        int c2 = __popc(bal);
        g_inv[qid] = 1.0f / (float)(c2 > 0 ? c2 : 1);
    }
    __syncwarp();

    const float* fb = s_feats + lane * 2;
    __half* dst = &g_kf16[(size_t)qid * KDIM + lane * 2];
    int base2 = 0;
    #pragma unroll
    for (int e = 0; e < KPN; e++) {
        int c = cnt[e];
        if (c) {                                 // warp-uniform
            unsigned long long acc = 0ull;
            const float2* pp = plist + base2;
            #pragma unroll 4
            for (int i = 0; i < c; i++) {
                float2 p = pp[i];                // LDS.64 broadcast
                int id = __float_as_int(p.y);
                unsigned long long hv, f2;
                asm("mov.b64 %0, {%1, %1};" : "=l"(hv) : "f"(p.x));
                f2 = *reinterpret_cast<const unsigned long long*>(
                         &fb[(size_t)id * CIN]);
                asm("fma.rn.f32x2 %0, %1, %2, %0;" : "+l"(acc) : "l"(f2), "l"(hv));
            }
            float lo, hi;
            asm("mov.b64 {%0, %1}, %2;" : "=f"(lo), "=f"(hi) : "l"(acc));
            *reinterpret_cast<__half2*>(&dst[e * CIN]) = __floats2half2_rn(lo, hi);
            base2 += c;
        }
    }
}

// ---------------------------------------------------------------------------
// k2: fp16 HMMA GEMM, BM=64 tiles for 3 CTAs/SM (6 warps/SMSP -> saturate
// the HMMA pipe). C[50048,128] = A @ W^T', row-scaled by g_inv.
// 8 warps (2x4), warp tile 32x32, 3-stage cp.async, K=64 per chunk.
// ---------------------------------------------------------------------------
#define BM2   64
#define KCH   64
#define NCH   (KDIM / KCH)     // 15
#define NSTG  3
#define A_ST  (BM2 * 128)      // 8192 B per A stage
#define B_ST  (COUT * 128)     // 16384 B per B stage

extern __shared__ __align__(16) unsigned char k2_dsm[];

__device__ __forceinline__ void cpa16s(unsigned dst, const __half* src)
{
    asm volatile("cp.async.cg.shared.global [%0], [%1], 16;\n" :: "r"(dst), "l"(src));
}

__global__ __launch_bounds__(256, 3) void k2_gemm(float* __restrict__ out)
{
    const unsigned as_u = (unsigned)__cvta_generic_to_shared(k2_dsm);
    const unsigned bs_u = as_u + NSTG * A_ST;

    const int tid  = threadIdx.x;
    const int wid  = tid >> 5;
    const int lane = tid & 31;
    const int g = lane >> 2;
    const int t = lane & 3;
    const int warp_m = wid & 1;       // 32 rows each
    const int warp_n = wid >> 1;      // 32 cols each
    const int m0 = blockIdx.x * BM2;

    const __half* A = g_kf16;
    const __half* B = g_wtT16;

    float c[2][4][4];
    #pragma unroll
    for (int mt = 0; mt < 2; mt++)
        #pragma unroll
        for (int nt = 0; nt < 4; nt++)
            #pragma unroll
            for (int r = 0; r < 4; r++) c[mt][nt][r] = 0.0f;

    auto load_tiles = [&](int stage, int k0) {
        unsigned as = as_u + stage * A_ST;
        unsigned bs = bs_u + stage * B_ST;
        #pragma unroll
        for (int it = 0; it < 2; it++) {
            int lin = tid + it * 256;            // 0..511
            int row = lin >> 3, gr = lin & 7;
            int gsw = gr ^ (row & 7);
            cpa16s(as + (row * 8 + gsw) * 16,
                   &A[(size_t)(m0 + row) * KDIM + k0 + gr * 8]);
        }
        #pragma unroll
        for (int it = 0; it < 4; it++) {
            int lin = tid + it * 256;            // 0..1023
            int row = lin >> 3, gr = lin & 7;
            int gsw = gr ^ (row & 7);
            cpa16s(bs + (row * 8 + gsw) * 16,
                   &B[(size_t)row * KDIM + k0 + gr * 8]);
        }
    };

    load_tiles(0, 0);
    asm volatile("cp.async.commit_group;");
    load_tiles(1, KCH);
    asm volatile("cp.async.commit_group;");

    int cs = 0, ls = 2;
    for (int kc = 0; kc < NCH; kc++) {
        asm volatile("cp.async.wait_group 1;");
        __syncthreads();

        if (kc + 2 < NCH) {
            load_tiles(ls, (kc + 2) * KCH);
            ls = (ls == NSTG - 1) ? 0 : ls + 1;
        }
        asm volatile("cp.async.commit_group;");

        unsigned as = as_u + cs * A_ST;
        unsigned bs = bs_u + cs * B_ST;
        cs = (cs == NSTG - 1) ? 0 : cs + 1;

        #pragma unroll
        for (int kq = 0; kq < 4; kq++) {
            unsigned a_[2][4], b_[4][2];
            #pragma unroll
            for (int mt = 0; mt < 2; mt++) {
                int row = warp_m * 32 + mt * 16 + (lane & 15);
                int gr  = kq * 2 + (lane >> 4);
                unsigned addr = as + (row * 8 + (gr ^ (row & 7))) * 16;
                asm volatile(
                    "ldmatrix.sync.aligned.m8n8.x4.shared.b16 {%0,%1,%2,%3}, [%4];"
                    : "=r"(a_[mt][0]), "=r"(a_[mt][1]),
                      "=r"(a_[mt][2]), "=r"(a_[mt][3]) : "r"(addr));
            }
            #pragma unroll
            for (int cb = 0; cb < 2; cb++) {
                int which  = lane >> 3;
                int nt_loc = cb * 2 + (which >> 1);
                int kh     = which & 1;
                int row = warp_n * 32 + nt_loc * 8 + (lane & 7);
                int gr  = kq * 2 + kh;
                unsigned addr = bs + (row * 8 + (gr ^ (row & 7))) * 16;
                asm volatile(
                    "ldmatrix.sync.aligned.m8n8.x4.shared.b16 {%0,%1,%2,%3}, [%4];"
                    : "=r"(b_[cb * 2][0]),     "=r"(b_[cb * 2][1]),
                      "=r"(b_[cb * 2 + 1][0]), "=r"(b_[cb * 2 + 1][1]) : "r"(addr));
            }
            #pragma unroll
            for (int mt = 0; mt < 2; mt++)
                #pragma unroll
                for (int nt = 0; nt < 4; nt++)
                    asm volatile(
                        "mma.sync.aligned.m16n8k16.row.col.f32.f16.f16.f32 "
                        "{%0,%1,%2,%3}, {%4,%5,%6,%7}, {%8,%9}, {%0,%1,%2,%3};"
                        : "+f"(c[mt][nt][0]), "+f"(c[mt][nt][1]),
                          "+f"(c[mt][nt][2]), "+f"(c[mt][nt][3])
                        : "r"(a_[mt][0]), "r"(a_[mt][1]),
                          "r"(a_[mt][2]), "r"(a_[mt][3]),
                          "r"(b_[nt][0]), "r"(b_[nt][1]));
        }
    }

    // epilogue: scale by g_inv, store
    #pragma unroll
    for (int mt = 0; mt < 2; mt++) {
        int r0 = m0 + warp_m * 32 + mt * 16 + g;
        int r1 = r0 + 8;
        float inv0 = g_inv[r0];
        float inv1 = g_inv[r1];
        #pragma unroll
        for (int nt = 0; nt < 4; nt++) {
            int col = warp_n * 32 + nt * 8 + t * 2;
            if (r0 < N_Q)
                *(float2*)&out[(size_t)r0 * COUT + col] =
                    make_float2(c[mt][nt][0] * inv0, c[mt][nt][1] * inv0);
            if (r1 < N_Q)
                *(float2*)&out[(size_t)r1 * COUT + col] =
                    make_float2(c[mt][nt][2] * inv1, c[mt][nt][3] * inv1);
        }
    }
}

// ---------------------------------------------------------------------------
extern "C" void kernel_launch(void* const* d_in, const int* in_sizes, int n_in,
                              void* d_out, int out_size)
{
    const float* q_pts   = (const float*)d_in[0];
    const float* s_pts   = (const float*)d_in[1];
    const float* s_feats = (const float*)d_in[2];
    const int*   nidx    = (const int*)  d_in[3];
    const float* W       = (const float*)d_in[4];
    const float* kpts    = (const float*)d_in[5];
    float* out = (float*)d_out;

    const int k2smem = NSTG * (A_ST + B_ST);   // 73728 B
    cudaFuncSetAttribute(k2_gemm,
        cudaFuncAttributeMaxDynamicSharedMemorySize, k2smem);

    k0_prep<<<391 + 15, 256>>>(s_feats, W);
    k1_gather<<<N_Q / NW1, NW1 * 32>>>(q_pts, s_pts, s_feats, nidx, kpts);
    k2_gemm<<<M_PAD / BM2, 256, k2smem>>>(out);
}